// round 1
// baseline (speedup 1.0000x reference)
#include <cuda_runtime.h>
#include <cuda_fp16.h>
#include <cstdint>

#define NN   4096
#define EE   8
#define HH   128
#define MAXW 96
#define MSGW (2*EE*HH)   /* 2048 */
#define G3   384
#define TSTEPS 4

// ----------------------------------------------------------------------------
// Device-global scratch (allocation-free contract: __device__ globals)
// ----------------------------------------------------------------------------
__device__ int    g_cnt_out[EE*NN];
__device__ int    g_cnt_in [EE*NN];
__device__ int    g_ell_out[EE*NN*MAXW];
__device__ int    g_ell_in [EE*NN*MAXW];
__device__ __half g_hs_out [EE*NN*HH];
__device__ __half g_hs_in  [EE*NN*HH];
__device__ float  g_msg    [NN*MSGW];
__device__ float  g_gx     [NN*G3];
__device__ float  g_gh     [NN*G3];
__device__ float  g_emb    [NN*128];
__device__ float  g_init   [NN*144];

// ----------------------------------------------------------------------------
// Sparse build: scan dense adjacency once, append nonzero column/row indices.
// Adjacency entries are exactly 0.0f / 1.0f.
// ----------------------------------------------------------------------------
__global__ void build_kernel(const float* __restrict__ A) {
    long i = (long)blockIdx.x * blockDim.x + threadIdx.x;   // float4 index
    const float4 v = reinterpret_cast<const float4*>(A)[i];
    long base = i << 2;
    float vals[4] = {v.x, v.y, v.z, v.w};
#pragma unroll
    for (int j = 0; j < 4; j++) {
        if (vals[j] != 0.0f) {
            long idx = base + j;
            int c = (int)(idx & 4095);
            int r = (int)((idx >> 12) & 4095);
            int e = (int)(idx >> 24);
            int ro = (e << 12) | r;
            int ci = (e << 12) | c;
            int s = atomicAdd(&g_cnt_out[ro], 1);
            if (s < MAXW) g_ell_out[ro * MAXW + s] = c;
            int s2 = atomicAdd(&g_cnt_in[ci], 1);
            if (s2 < MAXW) g_ell_in[ci * MAXW + s2] = r;
        }
    }
}

// Sort each ELL row ascending -> deterministic summation order.
__global__ void sort_kernel() {
    int gw = blockIdx.x * blockDim.x + threadIdx.x;
    if (gw >= 2 * EE * NN) return;
    int r = (gw < EE * NN) ? gw : gw - EE * NN;
    int* ell       = (gw < EE * NN) ? g_ell_out : g_ell_in;
    const int* cnt = (gw < EE * NN) ? g_cnt_out : g_cnt_in;
    int c = cnt[r]; if (c > MAXW) c = MAXW;
    int* lst = ell + (long)r * MAXW;
    int buf[MAXW];
    for (int i = 0; i < c; i++) buf[i] = lst[i];
    for (int i = 1; i < c; i++) {
        int key = buf[i], k = i - 1;
        while (k >= 0 && buf[k] > key) { buf[k+1] = buf[k]; k--; }
        buf[k+1] = key;
    }
    for (int i = 0; i < c; i++) lst[i] = buf[i];
}

// ----------------------------------------------------------------------------
// Generic tiled NT GEMM:  C[M,N] = act(A[M,K] @ W[N,K]^T + bias)
// Requirements: M % 128 == 0, N % 128 == 0. K arbitrary (guarded).
// blockIdx.z = batch (strided) OR split-K chunk when ATOMIC=1.
// ----------------------------------------------------------------------------
#define BK 8

template<int ACT, int ATOMIC, typename OutT>
__global__ void __launch_bounds__(256)
gemm_nt(const float* __restrict__ A, int lda, long sA,
        const float* __restrict__ W, int ldw, long sW,
        const float* __restrict__ bias, long sB,
        OutT* __restrict__ C, int ldc, long sC,
        int K, int kChunk)
{
    const int z = blockIdx.z;
    A += (long)z * sA;  W += (long)z * sW;  C += (long)z * sC;
    if (bias) bias += (long)z * sB;
    const int kStart = ATOMIC ? z * kChunk : 0;
    const int kEnd   = ATOMIC ? min(kStart + kChunk, K) : K;

    __shared__ float As[BK][128 + 4];
    __shared__ float Ws[BK][128 + 4];

    const int tx   = threadIdx.x;
    const int row0 = blockIdx.y * 128;
    const int col0 = blockIdx.x * 128;
    const int lm   = tx >> 1;
    const int lk4  = (tx & 1) << 2;
    const int tr   = (tx >> 4) << 3;
    const int tc   = (tx & 15) << 3;

    const bool alA = ((lda & 3) == 0);
    const bool alW = ((ldw & 3) == 0);

    float acc[8][8];
#pragma unroll
    for (int i = 0; i < 8; i++)
#pragma unroll
        for (int j = 0; j < 8; j++) acc[i][j] = 0.0f;

    const float* Ap = A + (long)(row0 + lm) * lda + lk4;
    const float* Wp = W + (long)(col0 + lm) * ldw + lk4;

    for (int k0 = kStart; k0 < kEnd; k0 += BK) {
        float a0, a1, a2, a3, w0, w1, w2, w3;
        if (alA && (k0 + lk4 + 3 < kEnd)) {
            float4 t = *reinterpret_cast<const float4*>(Ap + k0);
            a0 = t.x; a1 = t.y; a2 = t.z; a3 = t.w;
        } else {
            a0 = (k0 + lk4 + 0 < kEnd) ? Ap[k0 + 0] : 0.0f;
            a1 = (k0 + lk4 + 1 < kEnd) ? Ap[k0 + 1] : 0.0f;
            a2 = (k0 + lk4 + 2 < kEnd) ? Ap[k0 + 2] : 0.0f;
            a3 = (k0 + lk4 + 3 < kEnd) ? Ap[k0 + 3] : 0.0f;
        }
        if (alW && (k0 + lk4 + 3 < kEnd)) {
            float4 t = *reinterpret_cast<const float4*>(Wp + k0);
            w0 = t.x; w1 = t.y; w2 = t.z; w3 = t.w;
        } else {
            w0 = (k0 + lk4 + 0 < kEnd) ? Wp[k0 + 0] : 0.0f;
            w1 = (k0 + lk4 + 1 < kEnd) ? Wp[k0 + 1] : 0.0f;
            w2 = (k0 + lk4 + 2 < kEnd) ? Wp[k0 + 2] : 0.0f;
            w3 = (k0 + lk4 + 3 < kEnd) ? Wp[k0 + 3] : 0.0f;
        }
        __syncthreads();   // previous tile's compute done
        As[lk4 + 0][lm] = a0; As[lk4 + 1][lm] = a1;
        As[lk4 + 2][lm] = a2; As[lk4 + 3][lm] = a3;
        Ws[lk4 + 0][lm] = w0; Ws[lk4 + 1][lm] = w1;
        Ws[lk4 + 2][lm] = w2; Ws[lk4 + 3][lm] = w3;
        __syncthreads();

#pragma unroll
        for (int kk = 0; kk < BK; kk++) {
            float a[8], b[8];
            *reinterpret_cast<float4*>(&a[0]) = *reinterpret_cast<const float4*>(&As[kk][tr]);
            *reinterpret_cast<float4*>(&a[4]) = *reinterpret_cast<const float4*>(&As[kk][tr + 4]);
            *reinterpret_cast<float4*>(&b[0]) = *reinterpret_cast<const float4*>(&Ws[kk][tc]);
            *reinterpret_cast<float4*>(&b[4]) = *reinterpret_cast<const float4*>(&Ws[kk][tc + 4]);
#pragma unroll
            for (int i = 0; i < 8; i++)
#pragma unroll
                for (int j = 0; j < 8; j++)
                    acc[i][j] += a[i] * b[j];
        }
    }

#pragma unroll
    for (int i = 0; i < 8; i++) {
        int row = row0 + tr + i;
#pragma unroll
        for (int j = 0; j < 8; j++) {
            int col = col0 + tc + j;
            float v = acc[i][j];
            if constexpr (ATOMIC) {
                atomicAdd(reinterpret_cast<float*>(&C[(long)row * ldc + col]), v);
            } else {
                if (bias) v += bias[col];
                if (ACT == 1) v = tanhf(v);
                C[(long)row * ldc + col] = (OutT)v;
            }
        }
    }
}

// ----------------------------------------------------------------------------
// Concat [emb | states | size_and_pos] -> g_init [N,144]
// ----------------------------------------------------------------------------
__global__ void concat_kernel(const float* __restrict__ states,
                              const float* __restrict__ sp) {
    int i = blockIdx.x * blockDim.x + threadIdx.x;
    if (i >= NN * 144) return;
    int n = i / 144, j = i % 144;
    float v;
    if (j < 128)      v = g_emb[n * 128 + j];
    else if (j < 138) v = states[n * 10 + (j - 128)];
    else              v = sp[n * 6 + (j - 138)];
    g_init[i] = v;
}

// ----------------------------------------------------------------------------
// SpMM: binary adjacency -> sum of fp16 hs rows.  One warp per (dir,e,n) row.
// msg[n][dir*1024 + e*128 + h]
// ----------------------------------------------------------------------------
__global__ void spmm_kernel() {
    int gw   = (blockIdx.x << 3) + (threadIdx.x >> 5);
    int lane = threadIdx.x & 31;
    int dir  = gw >> 15;
    int en   = gw & 32767;
    const int*    cnt = dir ? g_cnt_in  : g_cnt_out;
    const int*    ell = dir ? g_ell_in  : g_ell_out;
    const __half* hs  = dir ? g_hs_in   : g_hs_out;

    int c = cnt[en]; if (c > MAXW) c = MAXW;
    const int* lst = ell + (long)en * MAXW;
    int e = en >> 12;
    int n = en & 4095;

    float a0 = 0.f, a1 = 0.f, a2 = 0.f, a3 = 0.f;
#pragma unroll 2
    for (int s = 0; s < c; s++) {
        int col = lst[s];
        const __half* p = hs + ((long)((e << 12) | col) << 7) + (lane << 2);
        uint2 u = *reinterpret_cast<const uint2*>(p);
        __half2 h0 = *reinterpret_cast<__half2*>(&u.x);
        __half2 h1 = *reinterpret_cast<__half2*>(&u.y);
        float2 f0 = __half22float2(h0);
        float2 f1 = __half22float2(h1);
        a0 += f0.x; a1 += f0.y; a2 += f1.x; a3 += f1.y;
    }
    float4 o = make_float4(a0, a1, a2, a3);
    *reinterpret_cast<float4*>(g_msg + (long)n * MSGW + (dir << 10) + (e << 7) + (lane << 2)) = o;
}

// ----------------------------------------------------------------------------
// LayerNorm-GRU elementwise update. One block (128 threads) per node.
// ----------------------------------------------------------------------------
__device__ __forceinline__ void stats128(float x, float* red, float& mean, float& var) {
    float s = x, q = x * x;
#pragma unroll
    for (int o = 16; o > 0; o >>= 1) {
        s += __shfl_xor_sync(0xffffffffu, s, o);
        q += __shfl_xor_sync(0xffffffffu, q, o);
    }
    int w = threadIdx.x >> 5;
    __syncthreads();                    // protect red[] reuse
    if ((threadIdx.x & 31) == 0) { red[w] = s; red[4 + w] = q; }
    __syncthreads();
    s = red[0] + red[1] + red[2] + red[3];
    q = red[4] + red[5] + red[6] + red[7];
    mean = s * (1.0f / 128.0f);
    var  = q * (1.0f / 128.0f) - mean * mean;
}

__global__ void gru_kernel(const float* __restrict__ bx,
                           const float* __restrict__ gamma,
                           const float* __restrict__ beta,
                           float* __restrict__ h) {
    __shared__ float red[8];
    int n = blockIdx.x, j = threadIdx.x;
    const float* gxr = g_gx + (long)n * G3;
    const float* ghr = g_gh + (long)n * G3;

    float xr = gxr[j]       + bx[j];
    float xz = gxr[128 + j] + bx[128 + j];
    float xn = gxr[256 + j] + bx[256 + j];
    float hr = ghr[j], hz = ghr[128 + j], hn = ghr[256 + j];
    float hv = h[(long)n * 128 + j];

    float m, v;
    float ar = xr + hr;
    stats128(ar, red, m, v);
    float r = 1.0f / (1.0f + expf(-((ar - m) * rsqrtf(v + 1e-5f) * gamma[j] + beta[j])));

    float az = xz + hz;
    stats128(az, red, m, v);
    float z = 1.0f / (1.0f + expf(-((az - m) * rsqrtf(v + 1e-5f) * gamma[128 + j] + beta[128 + j])));

    float an = xn + r * hn;
    stats128(an, red, m, v);
    float nn = tanhf((an - m) * rsqrtf(v + 1e-5f) * gamma[256 + j] + beta[256 + j]);

    h[(long)n * 128 + j] = (1.0f - z) * nn + z * hv;
}

// ----------------------------------------------------------------------------
// Host orchestration
// ----------------------------------------------------------------------------
extern "C" void kernel_launch(void* const* d_in, const int* in_sizes, int n_in,
                              void* d_out, int out_size) {
    (void)in_sizes; (void)n_in; (void)out_size;
    const float* adj    = (const float*)d_in[0];
    const float* states = (const float*)d_in[1];
    const float* vecs   = (const float*)d_in[3];
    const float* sp     = (const float*)d_in[4];
    const float* W_red  = (const float*)d_in[5];
    const float* b_red  = (const float*)d_in[6];
    const float* W_init = (const float*)d_in[7];
    const float* b_init = (const float*)d_in[8];
    const float* W_out  = (const float*)d_in[9];
    const float* b_out  = (const float*)d_in[10];
    const float* W_in   = (const float*)d_in[11];
    const float* b_in   = (const float*)d_in[12];
    const float* Wx     = (const float*)d_in[13];
    const float* bx     = (const float*)d_in[14];
    const float* Wh     = (const float*)d_in[15];
    const float* bh     = (const float*)d_in[16];
    const float* gamma  = (const float*)d_in[17];
    const float* beta   = (const float*)d_in[18];
    float* h = (float*)d_out;

    void *pco, *pci, *pgx_v;
    float *p_emb, *p_init, *p_msg, *p_gx, *p_gh;
    __half *p_hso, *p_hsi;
    cudaGetSymbolAddress(&pco, g_cnt_out);
    cudaGetSymbolAddress(&pci, g_cnt_in);
    cudaGetSymbolAddress(&pgx_v, g_gx);
    cudaGetSymbolAddress((void**)&p_emb,  g_emb);
    cudaGetSymbolAddress((void**)&p_init, g_init);
    cudaGetSymbolAddress((void**)&p_msg,  g_msg);
    cudaGetSymbolAddress((void**)&p_gx,   g_gx);
    cudaGetSymbolAddress((void**)&p_gh,   g_gh);
    cudaGetSymbolAddress((void**)&p_hso,  g_hs_out);
    cudaGetSymbolAddress((void**)&p_hsi,  g_hs_in);

    // ---- one-time sparse build (per call; deterministic after sort) ----
    cudaMemsetAsync(pco, 0, sizeof(int) * EE * NN, 0);
    cudaMemsetAsync(pci, 0, sizeof(int) * EE * NN, 0);
    build_kernel<<<(EE * NN * (NN / 4)) / 256, 256>>>(adj);
    sort_kernel<<<(2 * EE * NN + 255) / 256, 256>>>();

    // ---- init: emb = tanh(vecs @ W_red^T + b_red); h0 = tanh(init @ W_init^T + b_init)
    gemm_nt<1, 0, float><<<dim3(1, 32, 1), 256>>>(
        vecs, 300, 0, W_red, 300, 0, b_red, 0, p_emb, 128, 0, 300, 300);
    concat_kernel<<<(NN * 144 + 255) / 256, 256>>>(states, sp);
    gemm_nt<1, 0, float><<<dim3(1, 32, 1), 256>>>(
        p_init, 144, 0, W_init, 144, 0, b_init, 0, h, 128, 0, 144, 144);

    // ---- T message-passing + GRU steps ----
    for (int t = 0; t < TSTEPS; t++) {
        // hs_out[e] = tanh(h @ W_out_e^T + b_out_e)  (fp16 out), batched over e
        gemm_nt<1, 0, __half><<<dim3(1, 32, EE), 256>>>(
            h, 128, 0, W_out, 128, (long)HH * HH, b_out, HH,
            p_hso, 128, (long)NN * HH, 128, 128);
        gemm_nt<1, 0, __half><<<dim3(1, 32, EE), 256>>>(
            h, 128, 0, W_in, 128, (long)HH * HH, b_in, HH,
            p_hsi, 128, (long)NN * HH, 128, 128);

        // sparse message aggregation -> msg [N, 2048]
        spmm_kernel<<<8192, 256>>>();

        // gx = msg @ Wx^T   (split-K=4, fp32 atomic accumulate; bias added in GRU)
        cudaMemsetAsync(pgx_v, 0, sizeof(float) * NN * G3, 0);
        gemm_nt<0, 1, float><<<dim3(3, 32, 4), 256>>>(
            p_msg, 2048, 0, Wx, 2048, 0, nullptr, 0,
            p_gx, G3, 0, 2048, 512);

        // gh = h @ Wh^T + bh
        gemm_nt<0, 0, float><<<dim3(3, 32, 1), 256>>>(
            h, 128, 0, Wh, 128, 0, bh, 0, p_gh, G3, 0, 128, 128);

        // LayerNorm-GRU update (in-place on h)
        gru_kernel<<<NN, 128>>>(bx, gamma, beta, h);
    }
}

// round 3
// speedup vs baseline: 1.8655x; 1.8655x over previous
#include <cuda_runtime.h>
#include <cuda_fp16.h>
#include <cstdint>

#define NN   4096
#define EE   8
#define HH   128
#define MAXW 96
#define MSGW (2*EE*HH)   /* 2048 */
#define G3   384
#define TSTEPS 4

// ----------------------------------------------------------------------------
// Device-global scratch (allocation-free contract)
// ----------------------------------------------------------------------------
__device__ int    g_cnt_out[EE*NN];
__device__ int    g_cnt_in [EE*NN];
__device__ int    g_ell_out[EE*NN*MAXW];
__device__ int    g_ell_in [EE*NN*MAXW];
__device__ __half g_hs16  [NN*MSGW];     // [n][dir*1024 + e*128 + h]
__device__ __half g_msg16 [NN*MSGW];
__device__ __half g_h16   [NN*HH];
__device__ __half g_Wcat16[MSGW*HH];     // rows: dir*1024+e*128+j -> W_*[e][j][:]
__device__ __half g_Wx16  [G3*MSGW];
__device__ __half g_Wh16  [G3*HH];
__device__ float  g_bcat  [MSGW];
__device__ float  g_gx    [NN*G3];
__device__ float  g_gh    [NN*G3];
__device__ float  g_emb   [NN*128];
__device__ float  g_init  [NN*144];

// ----------------------------------------------------------------------------
// Sparse build: scan dense adjacency once, append nonzero indices.
// ----------------------------------------------------------------------------
__global__ void build_kernel(const float* __restrict__ A) {
    long i = (long)blockIdx.x * blockDim.x + threadIdx.x;   // float4 index
    const float4 v = reinterpret_cast<const float4*>(A)[i];
    long base = i << 2;
    float vals[4] = {v.x, v.y, v.z, v.w};
#pragma unroll
    for (int j = 0; j < 4; j++) {
        if (vals[j] != 0.0f) {
            long idx = base + j;
            int c = (int)(idx & 4095);
            int r = (int)((idx >> 12) & 4095);
            int e = (int)(idx >> 24);
            int ro = (e << 12) | r;
            int ci = (e << 12) | c;
            int s = atomicAdd(&g_cnt_out[ro], 1);
            if (s < MAXW) g_ell_out[ro * MAXW + s] = c;
            int s2 = atomicAdd(&g_cnt_in[ci], 1);
            if (s2 < MAXW) g_ell_in[ci * MAXW + s2] = r;
        }
    }
}

// Sort each ELL row ascending -> deterministic summation order.
__global__ void sort_kernel() {
    int gw = blockIdx.x * blockDim.x + threadIdx.x;
    if (gw >= 2 * EE * NN) return;
    int r = (gw < EE * NN) ? gw : gw - EE * NN;
    int* ell       = (gw < EE * NN) ? g_ell_out : g_ell_in;
    const int* cnt = (gw < EE * NN) ? g_cnt_out : g_cnt_in;
    int c = cnt[r]; if (c > MAXW) c = MAXW;
    int* lst = ell + (long)r * MAXW;
    int buf[MAXW];
    for (int i = 0; i < c; i++) buf[i] = lst[i];
    for (int i = 1; i < c; i++) {
        int key = buf[i], k = i - 1;
        while (k >= 0 && buf[k] > key) { buf[k+1] = buf[k]; k--; }
        buf[k+1] = key;
    }
    for (int i = 0; i < c; i++) lst[i] = buf[i];
}

// ----------------------------------------------------------------------------
// fp32 -> fp16 convert (weights / h)
// ----------------------------------------------------------------------------
__global__ void f2h_kernel(const float* __restrict__ s, __half* __restrict__ d, int n) {
    int i = blockIdx.x * blockDim.x + threadIdx.x;
    if (i < n) d[i] = __float2half(s[i]);
}

// ----------------------------------------------------------------------------
// HMMA GEMM:  C[M,N] = act(A16[M,K] @ B16[N,K]^T + bias)
// A16, B16 fp16 row-major. M%128==0, N%128==0, K%32==0.
// Block 128x128, 256 threads = 8 warps (2x4), warp tile 64x32.
// ----------------------------------------------------------------------------
__device__ __forceinline__ void ldsm4(uint32_t* r, uint32_t addr) {
    asm volatile("ldmatrix.sync.aligned.m8n8.x4.shared.b16 {%0,%1,%2,%3}, [%4];\n"
        : "=r"(r[0]), "=r"(r[1]), "=r"(r[2]), "=r"(r[3]) : "r"(addr));
}
__device__ __forceinline__ void mma16816(float* c, const uint32_t* a, const uint32_t* b) {
    asm volatile("mma.sync.aligned.m16n8k16.row.col.f32.f16.f16.f32 "
        "{%0,%1,%2,%3}, {%4,%5,%6,%7}, {%8,%9}, {%0,%1,%2,%3};\n"
        : "+f"(c[0]), "+f"(c[1]), "+f"(c[2]), "+f"(c[3])
        : "r"(a[0]), "r"(a[1]), "r"(a[2]), "r"(a[3]), "r"(b[0]), "r"(b[1]));
}

#define SLD 40   // smem row stride in halves (padded: conflict-free ldmatrix)

template<int ACT, typename OutT>
__global__ void __launch_bounds__(256)
hgemm(const __half* __restrict__ A, int lda,
      const __half* __restrict__ Bm, int ldb,
      const float* __restrict__ bias,
      OutT* __restrict__ C, int ldc, int K)
{
    __shared__ __half sA[128 * SLD];
    __shared__ __half sB[128 * SLD];

    const int tid  = threadIdx.x;
    const int lane = tid & 31;
    const int warp = tid >> 5;
    const int wr   = warp >> 2;        // 0..1  (64-row slab)
    const int wc   = warp & 3;         // 0..3  (32-col slab)
    const int row0 = blockIdx.y * 128;
    const int col0 = blockIdx.x * 128;

    float acc[4][4][4];
#pragma unroll
    for (int i = 0; i < 4; i++)
#pragma unroll
        for (int j = 0; j < 4; j++)
#pragma unroll
            for (int q = 0; q < 4; q++) acc[i][j][q] = 0.0f;

    const uint32_t aBase = (uint32_t)__cvta_generic_to_shared(sA);
    const uint32_t bBase = (uint32_t)__cvta_generic_to_shared(sB);

    // ldmatrix source rows (within tile) per lane
    const int aRow  = (lane & 15);                       // A: m 0-15
    const int aKoff = (lane >> 4) << 3;                  // A: k 0 / 8
    const int bRow  = (lane & 7) | ((lane & 16) >> 1);   // B: n 0-7 / 8-15
    const int bKoff = (lane & 8);                        // B: k 0 / 8

    for (int k0 = 0; k0 < K; k0 += 32) {
        __syncthreads();
#pragma unroll
        for (int i = 0; i < 2; i++) {
            int c  = tid + (i << 8);
            int r  = c >> 2;
            int kc = c & 3;
            *reinterpret_cast<int4*>(&sA[r * SLD + kc * 8]) =
                *reinterpret_cast<const int4*>(&A[(long)(row0 + r) * lda + k0 + kc * 8]);
            *reinterpret_cast<int4*>(&sB[r * SLD + kc * 8]) =
                *reinterpret_cast<const int4*>(&Bm[(long)(col0 + r) * ldb + k0 + kc * 8]);
        }
        __syncthreads();

#pragma unroll
        for (int kk = 0; kk < 2; kk++) {
            uint32_t a[4][4], b[4][2];
#pragma unroll
            for (int mt = 0; mt < 4; mt++) {
                uint32_t addr = aBase +
                    (uint32_t)(((wr * 64 + mt * 16 + aRow) * SLD + kk * 16 + aKoff) * 2);
                ldsm4(a[mt], addr);
            }
#pragma unroll
            for (int j = 0; j < 2; j++) {
                uint32_t r4[4];
                uint32_t addr = bBase +
                    (uint32_t)(((wc * 32 + j * 16 + bRow) * SLD + kk * 16 + bKoff) * 2);
                ldsm4(r4, addr);
                b[2 * j][0]     = r4[0]; b[2 * j][1]     = r4[1];
                b[2 * j + 1][0] = r4[2]; b[2 * j + 1][1] = r4[3];
            }
#pragma unroll
            for (int mt = 0; mt < 4; mt++)
#pragma unroll
                for (int nt = 0; nt < 4; nt++)
                    mma16816(acc[mt][nt], a[mt], b[nt]);
        }
    }

    // epilogue
    const int g   = lane >> 2;
    const int tc2 = (lane & 3) << 1;
#pragma unroll
    for (int mt = 0; mt < 4; mt++) {
        int r0 = row0 + wr * 64 + mt * 16 + g;
#pragma unroll
        for (int nt = 0; nt < 4; nt++) {
            int col = col0 + wc * 32 + nt * 8 + tc2;
            float b0 = 0.f, b1 = 0.f;
            if (bias) { b0 = bias[col]; b1 = bias[col + 1]; }
            float v00 = acc[mt][nt][0] + b0, v01 = acc[mt][nt][1] + b1;
            float v10 = acc[mt][nt][2] + b0, v11 = acc[mt][nt][3] + b1;
            if (ACT == 1) { v00 = tanhf(v00); v01 = tanhf(v01);
                            v10 = tanhf(v10); v11 = tanhf(v11); }
            if constexpr (sizeof(OutT) == 2) {
                __half2 p0 = __floats2half2_rn(v00, v01);
                __half2 p1 = __floats2half2_rn(v10, v11);
                *reinterpret_cast<__half2*>(&C[(long)r0 * ldc + col])       = p0;
                *reinterpret_cast<__half2*>(&C[(long)(r0 + 8) * ldc + col]) = p1;
            } else {
                *reinterpret_cast<float2*>(&C[(long)r0 * ldc + col])       = make_float2(v00, v01);
                *reinterpret_cast<float2*>(&C[(long)(r0 + 8) * ldc + col]) = make_float2(v10, v11);
            }
        }
    }
}

// ----------------------------------------------------------------------------
// fp32 SIMT GEMM (used only for the two once-per-call init GEMMs with odd K)
// ----------------------------------------------------------------------------
#define BK 8
template<int ACT, typename OutT>
__global__ void __launch_bounds__(256)
gemm_nt(const float* __restrict__ A, int lda,
        const float* __restrict__ W, int ldw,
        const float* __restrict__ bias,
        OutT* __restrict__ C, int ldc, int K)
{
    __shared__ float As[BK][128 + 4];
    __shared__ float Ws[BK][128 + 4];
    const int tx   = threadIdx.x;
    const int row0 = blockIdx.y * 128;
    const int col0 = blockIdx.x * 128;
    const int lm   = tx >> 1;
    const int lk4  = (tx & 1) << 2;
    const int tr   = (tx >> 4) << 3;
    const int tc   = (tx & 15) << 3;
    const bool alA = ((lda & 3) == 0);
    const bool alW = ((ldw & 3) == 0);

    float acc[8][8];
#pragma unroll
    for (int i = 0; i < 8; i++)
#pragma unroll
        for (int j = 0; j < 8; j++) acc[i][j] = 0.0f;

    const float* Ap = A + (long)(row0 + lm) * lda + lk4;
    const float* Wp = W + (long)(col0 + lm) * ldw + lk4;

    for (int k0 = 0; k0 < K; k0 += BK) {
        float a0, a1, a2, a3, w0, w1, w2, w3;
        if (alA && (k0 + lk4 + 3 < K)) {
            float4 t = *reinterpret_cast<const float4*>(Ap + k0);
            a0 = t.x; a1 = t.y; a2 = t.z; a3 = t.w;
        } else {
            a0 = (k0 + lk4 + 0 < K) ? Ap[k0 + 0] : 0.0f;
            a1 = (k0 + lk4 + 1 < K) ? Ap[k0 + 1] : 0.0f;
            a2 = (k0 + lk4 + 2 < K) ? Ap[k0 + 2] : 0.0f;
            a3 = (k0 + lk4 + 3 < K) ? Ap[k0 + 3] : 0.0f;
        }
        if (alW && (k0 + lk4 + 3 < K)) {
            float4 t = *reinterpret_cast<const float4*>(Wp + k0);
            w0 = t.x; w1 = t.y; w2 = t.z; w3 = t.w;
        } else {
            w0 = (k0 + lk4 + 0 < K) ? Wp[k0 + 0] : 0.0f;
            w1 = (k0 + lk4 + 1 < K) ? Wp[k0 + 1] : 0.0f;
            w2 = (k0 + lk4 + 2 < K) ? Wp[k0 + 2] : 0.0f;
            w3 = (k0 + lk4 + 3 < K) ? Wp[k0 + 3] : 0.0f;
        }
        __syncthreads();
        As[lk4 + 0][lm] = a0; As[lk4 + 1][lm] = a1;
        As[lk4 + 2][lm] = a2; As[lk4 + 3][lm] = a3;
        Ws[lk4 + 0][lm] = w0; Ws[lk4 + 1][lm] = w1;
        Ws[lk4 + 2][lm] = w2; Ws[lk4 + 3][lm] = w3;
        __syncthreads();
#pragma unroll
        for (int kk = 0; kk < BK; kk++) {
            float a[8], b[8];
            *reinterpret_cast<float4*>(&a[0]) = *reinterpret_cast<const float4*>(&As[kk][tr]);
            *reinterpret_cast<float4*>(&a[4]) = *reinterpret_cast<const float4*>(&As[kk][tr + 4]);
            *reinterpret_cast<float4*>(&b[0]) = *reinterpret_cast<const float4*>(&Ws[kk][tc]);
            *reinterpret_cast<float4*>(&b[4]) = *reinterpret_cast<const float4*>(&Ws[kk][tc + 4]);
#pragma unroll
            for (int i = 0; i < 8; i++)
#pragma unroll
                for (int j = 0; j < 8; j++)
                    acc[i][j] += a[i] * b[j];
        }
    }
#pragma unroll
    for (int i = 0; i < 8; i++) {
        int row = row0 + tr + i;
#pragma unroll
        for (int j = 0; j < 8; j++) {
            int col = col0 + tc + j;
            float v = acc[i][j];
            if (bias) v += bias[col];
            if (ACT == 1) v = tanhf(v);
            C[(long)row * ldc + col] = (OutT)v;
        }
    }
}

// ----------------------------------------------------------------------------
// Concat [emb | states | size_and_pos] -> g_init [N,144]
// ----------------------------------------------------------------------------
__global__ void concat_kernel(const float* __restrict__ states,
                              const float* __restrict__ sp) {
    int i = blockIdx.x * blockDim.x + threadIdx.x;
    if (i >= NN * 144) return;
    int n = i / 144, j = i % 144;
    float v;
    if (j < 128)      v = g_emb[n * 128 + j];
    else if (j < 138) v = states[n * 10 + (j - 128)];
    else              v = sp[n * 6 + (j - 138)];
    g_init[i] = v;
}

// ----------------------------------------------------------------------------
// SpMM: binary adjacency -> sum of fp16 hs rows.  One warp per (dir,e,n) row.
// Reads g_hs16 [n][dir*1024+e*128+h]; writes g_msg16 same layout (fp16).
// ----------------------------------------------------------------------------
__global__ void spmm_kernel() {
    int gw   = (blockIdx.x << 3) + (threadIdx.x >> 5);
    int lane = threadIdx.x & 31;
    int dir  = gw >> 15;
    int en   = gw & 32767;
    const int* cnt = dir ? g_cnt_in : g_cnt_out;
    const int* ell = dir ? g_ell_in : g_ell_out;

    int c = cnt[en]; if (c > MAXW) c = MAXW;
    const int* lst = ell + (long)en * MAXW;
    int e = en >> 12;
    int n = en & 4095;
    int fOff = (dir << 10) + (e << 7) + (lane << 2);

    float a0 = 0.f, a1 = 0.f, a2 = 0.f, a3 = 0.f;
#pragma unroll 2
    for (int s = 0; s < c; s++) {
        int col = lst[s];
        uint2 u = *reinterpret_cast<const uint2*>(&g_hs16[(long)col * MSGW + fOff]);
        __half2 h0 = *reinterpret_cast<__half2*>(&u.x);
        __half2 h1 = *reinterpret_cast<__half2*>(&u.y);
        float2 f0 = __half22float2(h0);
        float2 f1 = __half22float2(h1);
        a0 += f0.x; a1 += f0.y; a2 += f1.x; a3 += f1.y;
    }
    __half2 p0 = __floats2half2_rn(a0, a1);
    __half2 p1 = __floats2half2_rn(a2, a3);
    uint2 o;
    o.x = *reinterpret_cast<uint32_t*>(&p0);
    o.y = *reinterpret_cast<uint32_t*>(&p1);
    *reinterpret_cast<uint2*>(&g_msg16[(long)n * MSGW + fOff]) = o;
}

// ----------------------------------------------------------------------------
// LayerNorm-GRU elementwise update. One block (128 threads) per node.
// ----------------------------------------------------------------------------
__device__ __forceinline__ void stats128(float x, float* red, float& mean, float& var) {
    float s = x, q = x * x;
#pragma unroll
    for (int o = 16; o > 0; o >>= 1) {
        s += __shfl_xor_sync(0xffffffffu, s, o);
        q += __shfl_xor_sync(0xffffffffu, q, o);
    }
    int w = threadIdx.x >> 5;
    __syncthreads();
    if ((threadIdx.x & 31) == 0) { red[w] = s; red[4 + w] = q; }
    __syncthreads();
    s = red[0] + red[1] + red[2] + red[3];
    q = red[4] + red[5] + red[6] + red[7];
    mean = s * (1.0f / 128.0f);
    var  = q * (1.0f / 128.0f) - mean * mean;
}

__global__ void gru_kernel(const float* __restrict__ bx,
                           const float* __restrict__ gamma,
                           const float* __restrict__ beta,
                           float* __restrict__ h) {
    __shared__ float red[8];
    int n = blockIdx.x, j = threadIdx.x;
    const float* gxr = g_gx + (long)n * G3;
    const float* ghr = g_gh + (long)n * G3;

    float xr = gxr[j]       + bx[j];
    float xz = gxr[128 + j] + bx[128 + j];
    float xn = gxr[256 + j] + bx[256 + j];
    float hr = ghr[j], hz = ghr[128 + j], hn = ghr[256 + j];
    float hv = h[(long)n * 128 + j];

    float m, v;
    float ar = xr + hr;
    stats128(ar, red, m, v);
    float r = 1.0f / (1.0f + expf(-((ar - m) * rsqrtf(v + 1e-5f) * gamma[j] + beta[j])));

    float az = xz + hz;
    stats128(az, red, m, v);
    float z = 1.0f / (1.0f + expf(-((az - m) * rsqrtf(v + 1e-5f) * gamma[128 + j] + beta[128 + j])));

    float an = xn + r * hn;
    stats128(an, red, m, v);
    float nn = tanhf((an - m) * rsqrtf(v + 1e-5f) * gamma[256 + j] + beta[256 + j]);

    float hnew = (1.0f - z) * nn + z * hv;
    h[(long)n * 128 + j] = hnew;
    g_h16[(long)n * 128 + j] = __float2half(hnew);
}

// ----------------------------------------------------------------------------
// Host orchestration
// ----------------------------------------------------------------------------
extern "C" void kernel_launch(void* const* d_in, const int* in_sizes, int n_in,
                              void* d_out, int out_size) {
    (void)in_sizes; (void)n_in; (void)out_size;
    const float* adj    = (const float*)d_in[0];
    const float* states = (const float*)d_in[1];
    const float* vecs   = (const float*)d_in[3];
    const float* sp     = (const float*)d_in[4];
    const float* W_red  = (const float*)d_in[5];
    const float* b_red  = (const float*)d_in[6];
    const float* W_init = (const float*)d_in[7];
    const float* b_init = (const float*)d_in[8];
    const float* W_out  = (const float*)d_in[9];
    const float* b_out  = (const float*)d_in[10];
    const float* W_in   = (const float*)d_in[11];
    const float* b_in   = (const float*)d_in[12];
    const float* Wx     = (const float*)d_in[13];
    const float* bx     = (const float*)d_in[14];
    const float* Wh     = (const float*)d_in[15];
    const float* bh     = (const float*)d_in[16];
    const float* gamma  = (const float*)d_in[17];
    const float* beta   = (const float*)d_in[18];
    float* h = (float*)d_out;

    void *pco, *pci;
    float *p_emb, *p_init, *p_gx, *p_gh, *p_bcat;
    __half *p_hs, *p_msg, *p_h16, *p_Wcat, *p_Wx16, *p_Wh16;
    cudaGetSymbolAddress(&pco, g_cnt_out);
    cudaGetSymbolAddress(&pci, g_cnt_in);
    cudaGetSymbolAddress((void**)&p_emb,  g_emb);
    cudaGetSymbolAddress((void**)&p_init, g_init);
    cudaGetSymbolAddress((void**)&p_gx,   g_gx);
    cudaGetSymbolAddress((void**)&p_gh,   g_gh);
    cudaGetSymbolAddress((void**)&p_bcat, g_bcat);
    cudaGetSymbolAddress((void**)&p_hs,   g_hs16);
    cudaGetSymbolAddress((void**)&p_msg,  g_msg16);
    cudaGetSymbolAddress((void**)&p_h16,  g_h16);
    cudaGetSymbolAddress((void**)&p_Wcat, g_Wcat16);
    cudaGetSymbolAddress((void**)&p_Wx16, g_Wx16);
    cudaGetSymbolAddress((void**)&p_Wh16, g_Wh16);

    // ---- sparse build ----
    cudaMemsetAsync(pco, 0, sizeof(int) * EE * NN, 0);
    cudaMemsetAsync(pci, 0, sizeof(int) * EE * NN, 0);
    build_kernel<<<(EE * NN * (NN / 4)) / 256, 256>>>(adj);
    sort_kernel<<<(2 * EE * NN + 255) / 256, 256>>>();

    // ---- weight conversion / packing (fp16) ----
    f2h_kernel<<<(EE*HH*HH + 255)/256, 256>>>(W_out, p_Wcat,             EE*HH*HH);
    f2h_kernel<<<(EE*HH*HH + 255)/256, 256>>>(W_in,  p_Wcat + EE*HH*HH,  EE*HH*HH);
    f2h_kernel<<<(G3*MSGW  + 255)/256, 256>>>(Wx,    p_Wx16,             G3*MSGW);
    f2h_kernel<<<(G3*HH    + 255)/256, 256>>>(Wh,    p_Wh16,             G3*HH);
    cudaMemcpyAsync(p_bcat,           b_out, EE*HH*sizeof(float), cudaMemcpyDeviceToDevice, 0);
    cudaMemcpyAsync(p_bcat + EE*HH,   b_in,  EE*HH*sizeof(float), cudaMemcpyDeviceToDevice, 0);

    // ---- init: emb = tanh(vecs @ W_red^T); h0 = tanh(init @ W_init^T) ----
    gemm_nt<1, float><<<dim3(1, 32), 256>>>(vecs, 300, W_red, 300, b_red, p_emb, 128, 300);
    concat_kernel<<<(NN * 144 + 255) / 256, 256>>>(states, sp);
    gemm_nt<1, float><<<dim3(1, 32), 256>>>(p_init, 144, W_init, 144, b_init, h, 128, 144);
    f2h_kernel<<<(NN*HH + 255)/256, 256>>>(h, p_h16, NN*HH);

    // ---- T message-passing + GRU steps ----
    for (int t = 0; t < TSTEPS; t++) {
        // hs = tanh(h @ Wcat^T + bcat)  -> fp16 [N,2048], both dirs fused
        hgemm<1, __half><<<dim3(16, 32), 256>>>(p_h16, HH, p_Wcat, HH, p_bcat,
                                                p_hs, MSGW, HH);
        // sparse aggregation -> msg16 [N,2048]
        spmm_kernel<<<8192, 256>>>();
        // gx = msg @ Wx^T  (bias added in GRU)
        hgemm<0, float><<<dim3(3, 32), 256>>>(p_msg, MSGW, p_Wx16, MSGW, nullptr,
                                              p_gx, G3, MSGW);
        // gh = h @ Wh^T + bh
        hgemm<0, float><<<dim3(3, 32), 256>>>(p_h16, HH, p_Wh16, HH, bh,
                                              p_gh, G3, HH);
        // LayerNorm-GRU update (writes h fp32 + h16)
        gru_kernel<<<NN, 128>>>(bx, gamma, beta, h);
    }
}

// round 4
// speedup vs baseline: 2.1803x; 1.1687x over previous
#include <cuda_runtime.h>
#include <cuda_fp16.h>
#include <cstdint>

#define NN   4096
#define EE   8
#define HH   128
#define MAXW 96
#define MSGW (2*EE*HH)   /* 2048 */
#define G3   384
#define TSTEPS 4

// ----------------------------------------------------------------------------
// Device-global scratch (allocation-free contract)
// ----------------------------------------------------------------------------
__device__ int    g_cnt_out[EE*NN];
__device__ int    g_cnt_in [EE*NN];
__device__ int    g_ell_out[EE*NN*MAXW];
__device__ int    g_ell_in [EE*NN*MAXW];
__device__ __half g_hs16  [NN*MSGW];     // [n][dir*1024 + e*128 + h]
__device__ __half g_msg16 [NN*MSGW];
__device__ __half g_h16   [NN*HH];
__device__ __half g_Wcat16[MSGW*HH];     // rows: dir*1024+e*128+j -> W_*[e][j][:]
__device__ __half g_Wx16  [G3*MSGW];
__device__ __half g_Wh16  [G3*HH];
__device__ float  g_bcat  [MSGW];
__device__ float  g_gx    [NN*G3];
__device__ float  g_gh    [NN*G3];
__device__ __half g_vec16 [NN*320];      // node_vectors padded 300->320
__device__ __half g_init16[NN*160];      // [emb(128) | states(10) | sp(6) | pad(16)]
__device__ __half g_Wred16[128*320];
__device__ __half g_Winit16[128*160];

// ----------------------------------------------------------------------------
// Sparse build: scan dense adjacency once, append nonzero indices.
// ----------------------------------------------------------------------------
__global__ void build_kernel(const float* __restrict__ A) {
    long i = (long)blockIdx.x * blockDim.x + threadIdx.x;   // float4 index
    const float4 v = reinterpret_cast<const float4*>(A)[i];
    long base = i << 2;
    float vals[4] = {v.x, v.y, v.z, v.w};
#pragma unroll
    for (int j = 0; j < 4; j++) {
        if (vals[j] != 0.0f) {
            long idx = base + j;
            int c = (int)(idx & 4095);
            int r = (int)((idx >> 12) & 4095);
            int e = (int)(idx >> 24);
            int ro = (e << 12) | r;
            int ci = (e << 12) | c;
            int s = atomicAdd(&g_cnt_out[ro], 1);
            if (s < MAXW) g_ell_out[ro * MAXW + s] = c;
            int s2 = atomicAdd(&g_cnt_in[ci], 1);
            if (s2 < MAXW) g_ell_in[ci * MAXW + s2] = r;
        }
    }
}

// Sort each ELL row ascending -> deterministic summation order.
__global__ void sort_kernel() {
    int gw = blockIdx.x * blockDim.x + threadIdx.x;
    if (gw >= 2 * EE * NN) return;
    int r = (gw < EE * NN) ? gw : gw - EE * NN;
    int* ell       = (gw < EE * NN) ? g_ell_out : g_ell_in;
    const int* cnt = (gw < EE * NN) ? g_cnt_out : g_cnt_in;
    int c = cnt[r]; if (c > MAXW) c = MAXW;
    int* lst = ell + (long)r * MAXW;
    int buf[MAXW];
    for (int i = 0; i < c; i++) buf[i] = lst[i];
    for (int i = 1; i < c; i++) {
        int key = buf[i], k = i - 1;
        while (k >= 0 && buf[k] > key) { buf[k+1] = buf[k]; k--; }
        buf[k+1] = key;
    }
    for (int i = 0; i < c; i++) lst[i] = buf[i];
}

// ----------------------------------------------------------------------------
// Fused weight conversion / packing (all fp32 -> fp16, one launch)
// ----------------------------------------------------------------------------
#define N_WCAT (EE*HH*HH)        /* 131072 */
#define N_WX   (G3*MSGW)         /* 786432 */
#define N_WH   (G3*HH)           /* 49152 */
#define N_WRED (128*320)
#define N_WINI (128*160)
#define N_VEC  (NN*320)
#define PREP_TOTAL (2*N_WCAT + N_WX + N_WH + MSGW + N_WRED + N_WINI + N_VEC)

__global__ void prep_kernel(const float* __restrict__ W_out, const float* __restrict__ W_in,
                            const float* __restrict__ Wx,    const float* __restrict__ Wh,
                            const float* __restrict__ b_out, const float* __restrict__ b_in,
                            const float* __restrict__ W_red, const float* __restrict__ W_init,
                            const float* __restrict__ vecs) {
    int j = blockIdx.x * blockDim.x + threadIdx.x;
    if (j < N_WCAT) { g_Wcat16[j] = __float2half(W_out[j]); return; }
    j -= N_WCAT;
    if (j < N_WCAT) { g_Wcat16[N_WCAT + j] = __float2half(W_in[j]); return; }
    j -= N_WCAT;
    if (j < N_WX)   { g_Wx16[j] = __float2half(Wx[j]); return; }
    j -= N_WX;
    if (j < N_WH)   { g_Wh16[j] = __float2half(Wh[j]); return; }
    j -= N_WH;
    if (j < MSGW)   { g_bcat[j] = (j < EE*HH) ? b_out[j] : b_in[j - EE*HH]; return; }
    j -= MSGW;
    if (j < N_WRED) { int r = j / 320, c = j % 320;
                      g_Wred16[j] = __float2half(c < 300 ? W_red[r * 300 + c] : 0.f); return; }
    j -= N_WRED;
    if (j < N_WINI) { int r = j / 160, c = j % 160;
                      g_Winit16[j] = __float2half(c < 144 ? W_init[r * 144 + c] : 0.f); return; }
    j -= N_WINI;
    if (j < N_VEC)  { int r = j / 320, c = j % 320;
                      g_vec16[j] = __float2half(c < 300 ? vecs[r * 300 + c] : 0.f); }
}

// Fill cols 128..159 of g_init16 with [states(10) | sp(6) | zeros(16)]
__global__ void concat16_kernel(const float* __restrict__ states,
                                const float* __restrict__ sp) {
    int i = blockIdx.x * blockDim.x + threadIdx.x;
    if (i >= NN * 32) return;
    int n = i >> 5, j = i & 31;
    float v = (j < 10) ? states[n * 10 + j]
            : (j < 16) ? sp[n * 6 + (j - 10)]
            : 0.0f;
    g_init16[n * 160 + 128 + j] = __float2half(v);
}

// ----------------------------------------------------------------------------
// HMMA GEMM:  C[M,N] = act(A16[M,K] @ B16[N,K]^T + bias)
// A16, B16 fp16 row-major. M%128==0, N%128==0, K%32==0, lda/ldb %8==0.
// Block 128x128, 256 threads = 8 warps (2x4), warp tile 64x32.
// Optional second fp16 output C2 (same ldc).
// ----------------------------------------------------------------------------
__device__ __forceinline__ void ldsm4(uint32_t* r, uint32_t addr) {
    asm volatile("ldmatrix.sync.aligned.m8n8.x4.shared.b16 {%0,%1,%2,%3}, [%4];\n"
        : "=r"(r[0]), "=r"(r[1]), "=r"(r[2]), "=r"(r[3]) : "r"(addr));
}
__device__ __forceinline__ void mma16816(float* c, const uint32_t* a, const uint32_t* b) {
    asm volatile("mma.sync.aligned.m16n8k16.row.col.f32.f16.f16.f32 "
        "{%0,%1,%2,%3}, {%4,%5,%6,%7}, {%8,%9}, {%0,%1,%2,%3};\n"
        : "+f"(c[0]), "+f"(c[1]), "+f"(c[2]), "+f"(c[3])
        : "r"(a[0]), "r"(a[1]), "r"(a[2]), "r"(a[3]), "r"(b[0]), "r"(b[1]));
}

#define SLD 40   // smem row stride in halves (padded: conflict-free ldmatrix)

template<int ACT, typename OutT>
__global__ void __launch_bounds__(256)
hgemm(const __half* __restrict__ A, int lda,
      const __half* __restrict__ Bm, int ldb,
      const float* __restrict__ bias,
      OutT* __restrict__ C, int ldc,
      __half* __restrict__ C2, int K)
{
    __shared__ __half sA[128 * SLD];
    __shared__ __half sB[128 * SLD];

    const int tid  = threadIdx.x;
    const int lane = tid & 31;
    const int warp = tid >> 5;
    const int wr   = warp >> 2;        // 0..1  (64-row slab)
    const int wc   = warp & 3;         // 0..3  (32-col slab)
    const int row0 = blockIdx.y * 128;
    const int col0 = blockIdx.x * 128;

    float acc[4][4][4];
#pragma unroll
    for (int i = 0; i < 4; i++)
#pragma unroll
        for (int j = 0; j < 4; j++)
#pragma unroll
            for (int q = 0; q < 4; q++) acc[i][j][q] = 0.0f;

    const uint32_t aBase = (uint32_t)__cvta_generic_to_shared(sA);
    const uint32_t bBase = (uint32_t)__cvta_generic_to_shared(sB);

    const int aRow  = (lane & 15);
    const int aKoff = (lane >> 4) << 3;
    const int bRow  = (lane & 7) | ((lane & 16) >> 1);
    const int bKoff = (lane & 8);

    for (int k0 = 0; k0 < K; k0 += 32) {
        __syncthreads();
#pragma unroll
        for (int i = 0; i < 2; i++) {
            int c  = tid + (i << 8);
            int r  = c >> 2;
            int kc = c & 3;
            *reinterpret_cast<int4*>(&sA[r * SLD + kc * 8]) =
                *reinterpret_cast<const int4*>(&A[(long)(row0 + r) * lda + k0 + kc * 8]);
            *reinterpret_cast<int4*>(&sB[r * SLD + kc * 8]) =
                *reinterpret_cast<const int4*>(&Bm[(long)(col0 + r) * ldb + k0 + kc * 8]);
        }
        __syncthreads();

#pragma unroll
        for (int kk = 0; kk < 2; kk++) {
            uint32_t a[4][4], b[4][2];
#pragma unroll
            for (int mt = 0; mt < 4; mt++) {
                uint32_t addr = aBase +
                    (uint32_t)(((wr * 64 + mt * 16 + aRow) * SLD + kk * 16 + aKoff) * 2);
                ldsm4(a[mt], addr);
            }
#pragma unroll
            for (int j = 0; j < 2; j++) {
                uint32_t r4[4];
                uint32_t addr = bBase +
                    (uint32_t)(((wc * 32 + j * 16 + bRow) * SLD + kk * 16 + bKoff) * 2);
                ldsm4(r4, addr);
                b[2 * j][0]     = r4[0]; b[2 * j][1]     = r4[1];
                b[2 * j + 1][0] = r4[2]; b[2 * j + 1][1] = r4[3];
            }
#pragma unroll
            for (int mt = 0; mt < 4; mt++)
#pragma unroll
                for (int nt = 0; nt < 4; nt++)
                    mma16816(acc[mt][nt], a[mt], b[nt]);
        }
    }

    // epilogue
    const int g   = lane >> 2;
    const int tc2 = (lane & 3) << 1;
#pragma unroll
    for (int mt = 0; mt < 4; mt++) {
        int r0 = row0 + wr * 64 + mt * 16 + g;
#pragma unroll
        for (int nt = 0; nt < 4; nt++) {
            int col = col0 + wc * 32 + nt * 8 + tc2;
            float b0 = 0.f, b1 = 0.f;
            if (bias) { b0 = bias[col]; b1 = bias[col + 1]; }
            float v00 = acc[mt][nt][0] + b0, v01 = acc[mt][nt][1] + b1;
            float v10 = acc[mt][nt][2] + b0, v11 = acc[mt][nt][3] + b1;
            if (ACT == 1) { v00 = tanhf(v00); v01 = tanhf(v01);
                            v10 = tanhf(v10); v11 = tanhf(v11); }
            if constexpr (sizeof(OutT) == 2) {
                __half2 p0 = __floats2half2_rn(v00, v01);
                __half2 p1 = __floats2half2_rn(v10, v11);
                *reinterpret_cast<__half2*>(&C[(long)r0 * ldc + col])       = p0;
                *reinterpret_cast<__half2*>(&C[(long)(r0 + 8) * ldc + col]) = p1;
            } else {
                *reinterpret_cast<float2*>(&C[(long)r0 * ldc + col])       = make_float2(v00, v01);
                *reinterpret_cast<float2*>(&C[(long)(r0 + 8) * ldc + col]) = make_float2(v10, v11);
            }
            if (C2) {
                __half2 p0 = __floats2half2_rn(v00, v01);
                __half2 p1 = __floats2half2_rn(v10, v11);
                *reinterpret_cast<__half2*>(&C2[(long)r0 * ldc + col])       = p0;
                *reinterpret_cast<__half2*>(&C2[(long)(r0 + 8) * ldc + col]) = p1;
            }
        }
    }
}

// ----------------------------------------------------------------------------
// SpMM: binary adjacency -> sum of fp16 hs rows.  One warp per (dir,e,n) row.
// 2 edges in flight per iteration: lanes 0-15 take even s, 16-31 odd s.
// ----------------------------------------------------------------------------
__global__ void spmm_kernel() {
    int gw   = (blockIdx.x << 3) + (threadIdx.x >> 5);
    int lane = threadIdx.x & 31;
    int dir  = gw >> 15;
    int en   = gw & 32767;
    const int* cnt = dir ? g_cnt_in : g_cnt_out;
    const int* ell = dir ? g_ell_in : g_ell_out;

    int c = cnt[en]; if (c > MAXW) c = MAXW;
    const int* lst = ell + (long)en * MAXW;
    int e = en >> 12;
    int n = en & 4095;
    int base = (dir << 10) + (e << 7);
    int fl   = (lane & 15) << 3;    // feature start (8 halves per lane)
    int s0   = lane >> 4;           // 0 or 1

    float acc[8];
#pragma unroll
    for (int j = 0; j < 8; j++) acc[j] = 0.f;

#pragma unroll 2
    for (int s = s0; s < c; s += 2) {
        int col = lst[s];
        int4 u = *reinterpret_cast<const int4*>(&g_hs16[(long)col * MSGW + base + fl]);
        const __half2* hp = reinterpret_cast<const __half2*>(&u);
#pragma unroll
        for (int j = 0; j < 4; j++) {
            float2 f = __half22float2(hp[j]);
            acc[2 * j]     += f.x;
            acc[2 * j + 1] += f.y;
        }
    }
#pragma unroll
    for (int j = 0; j < 8; j++)
        acc[j] += __shfl_down_sync(0xffffffffu, acc[j], 16);

    if (lane < 16) {
        __half2 o[4];
#pragma unroll
        for (int j = 0; j < 4; j++) o[j] = __floats2half2_rn(acc[2 * j], acc[2 * j + 1]);
        *reinterpret_cast<int4*>(&g_msg16[(long)n * MSGW + base + fl]) =
            *reinterpret_cast<const int4*>(o);
    }
}

// ----------------------------------------------------------------------------
// LayerNorm-GRU elementwise update. One block (128 threads) per node.
// ----------------------------------------------------------------------------
__device__ __forceinline__ void stats128(float x, float* red, float& mean, float& var) {
    float s = x, q = x * x;
#pragma unroll
    for (int o = 16; o > 0; o >>= 1) {
        s += __shfl_xor_sync(0xffffffffu, s, o);
        q += __shfl_xor_sync(0xffffffffu, q, o);
    }
    int w = threadIdx.x >> 5;
    __syncthreads();
    if ((threadIdx.x & 31) == 0) { red[w] = s; red[4 + w] = q; }
    __syncthreads();
    s = red[0] + red[1] + red[2] + red[3];
    q = red[4] + red[5] + red[6] + red[7];
    mean = s * (1.0f / 128.0f);
    var  = q * (1.0f / 128.0f) - mean * mean;
}

__global__ void gru_kernel(const float* __restrict__ bx,
                           const float* __restrict__ gamma,
                           const float* __restrict__ beta,
                           float* __restrict__ h) {
    __shared__ float red[8];
    int n = blockIdx.x, j = threadIdx.x;
    const float* gxr = g_gx + (long)n * G3;
    const float* ghr = g_gh + (long)n * G3;

    float xr = gxr[j]       + bx[j];
    float xz = gxr[128 + j] + bx[128 + j];
    float xn = gxr[256 + j] + bx[256 + j];
    float hr = ghr[j], hz = ghr[128 + j], hn = ghr[256 + j];
    float hv = h[(long)n * 128 + j];

    float m, v;
    float ar = xr + hr;
    stats128(ar, red, m, v);
    float r = 1.0f / (1.0f + expf(-((ar - m) * rsqrtf(v + 1e-5f) * gamma[j] + beta[j])));

    float az = xz + hz;
    stats128(az, red, m, v);
    float z = 1.0f / (1.0f + expf(-((az - m) * rsqrtf(v + 1e-5f) * gamma[128 + j] + beta[128 + j])));

    float an = xn + r * hn;
    stats128(an, red, m, v);
    float nn = tanhf((an - m) * rsqrtf(v + 1e-5f) * gamma[256 + j] + beta[256 + j]);

    float hnew = (1.0f - z) * nn + z * hv;
    h[(long)n * 128 + j] = hnew;
    g_h16[(long)n * 128 + j] = __float2half(hnew);
}

// ----------------------------------------------------------------------------
// Host orchestration
// ----------------------------------------------------------------------------
extern "C" void kernel_launch(void* const* d_in, const int* in_sizes, int n_in,
                              void* d_out, int out_size) {
    (void)in_sizes; (void)n_in; (void)out_size;
    const float* adj    = (const float*)d_in[0];
    const float* states = (const float*)d_in[1];
    const float* vecs   = (const float*)d_in[3];
    const float* sp     = (const float*)d_in[4];
    const float* W_red  = (const float*)d_in[5];
    const float* b_red  = (const float*)d_in[6];
    const float* W_init = (const float*)d_in[7];
    const float* b_init = (const float*)d_in[8];
    const float* W_out  = (const float*)d_in[9];
    const float* b_out  = (const float*)d_in[10];
    const float* W_in   = (const float*)d_in[11];
    const float* b_in   = (const float*)d_in[12];
    const float* Wx     = (const float*)d_in[13];
    const float* bx     = (const float*)d_in[14];
    const float* Wh     = (const float*)d_in[15];
    const float* bh     = (const float*)d_in[16];
    const float* gamma  = (const float*)d_in[17];
    const float* beta   = (const float*)d_in[18];
    float* h = (float*)d_out;

    void *pco, *pci;
    float *p_gx, *p_gh, *p_bcat;
    __half *p_hs, *p_msg, *p_h16, *p_Wcat, *p_Wx16, *p_Wh16;
    __half *p_vec16, *p_init16, *p_Wred16, *p_Winit16;
    cudaGetSymbolAddress(&pco, g_cnt_out);
    cudaGetSymbolAddress(&pci, g_cnt_in);
    cudaGetSymbolAddress((void**)&p_gx,     g_gx);
    cudaGetSymbolAddress((void**)&p_gh,     g_gh);
    cudaGetSymbolAddress((void**)&p_bcat,   g_bcat);
    cudaGetSymbolAddress((void**)&p_hs,     g_hs16);
    cudaGetSymbolAddress((void**)&p_msg,    g_msg16);
    cudaGetSymbolAddress((void**)&p_h16,    g_h16);
    cudaGetSymbolAddress((void**)&p_Wcat,   g_Wcat16);
    cudaGetSymbolAddress((void**)&p_Wx16,   g_Wx16);
    cudaGetSymbolAddress((void**)&p_Wh16,   g_Wh16);
    cudaGetSymbolAddress((void**)&p_vec16,  g_vec16);
    cudaGetSymbolAddress((void**)&p_init16, g_init16);
    cudaGetSymbolAddress((void**)&p_Wred16, g_Wred16);
    cudaGetSymbolAddress((void**)&p_Winit16,g_Winit16);

    // ---- sparse build ----
    cudaMemsetAsync(pco, 0, sizeof(int) * EE * NN, 0);
    cudaMemsetAsync(pci, 0, sizeof(int) * EE * NN, 0);
    build_kernel<<<(EE * NN * (NN / 4)) / 256, 256>>>(adj);
    sort_kernel<<<(2 * EE * NN + 255) / 256, 256>>>();

    // ---- fused weight conversion / packing ----
    prep_kernel<<<(PREP_TOTAL + 255) / 256, 256>>>(
        W_out, W_in, Wx, Wh, b_out, b_in, W_red, W_init, vecs);

    // ---- init: emb = tanh(vec16 @ Wred16^T) -> init16 cols 0..127 ----
    hgemm<1, __half><<<dim3(1, 32), 256>>>(p_vec16, 320, p_Wred16, 320, b_red,
                                           p_init16, 160, nullptr, 320);
    concat16_kernel<<<(NN * 32 + 255) / 256, 256>>>(states, sp);
    // h0 = tanh(init16 @ Winit16^T)  -> h (fp32) + h16
    hgemm<1, float><<<dim3(1, 32), 256>>>(p_init16, 160, p_Winit16, 160, b_init,
                                          h, 128, p_h16, 160);

    // ---- T message-passing + GRU steps ----
    for (int t = 0; t < TSTEPS; t++) {
        // hs = tanh(h @ Wcat^T + bcat)  -> fp16 [N,2048], both dirs fused
        hgemm<1, __half><<<dim3(16, 32), 256>>>(p_h16, HH, p_Wcat, HH, p_bcat,
                                                p_hs, MSGW, nullptr, HH);
        // sparse aggregation -> msg16 [N,2048]
        spmm_kernel<<<8192, 256>>>();
        // gx = msg @ Wx^T  (bias added in GRU)
        hgemm<0, float><<<dim3(3, 32), 256>>>(p_msg, MSGW, p_Wx16, MSGW, nullptr,
                                              p_gx, G3, nullptr, MSGW);
        // gh = h @ Wh^T + bh
        hgemm<0, float><<<dim3(3, 32), 256>>>(p_h16, HH, p_Wh16, HH, bh,
                                              p_gh, G3, nullptr, HH);
        // LayerNorm-GRU update (writes h fp32 + h16)
        gru_kernel<<<NN, 128>>>(bx, gamma, beta, h);
    }
}